// round 1
// baseline (speedup 1.0000x reference)
#include <cuda_runtime.h>

// Problem: B=8, IC=512, H=W=64
//   m[b,j]   = sum_c x[b,c,j]*w[c] + cb                (j = h*64+w, 0..4095)
//   BN(train, biased var) over all 32768 m, then PReLU -> X[b,j]
//   Xn = X / sqrt(sum_b X^2)   (per column j)
//   r[b] = (1/64) * sum_j Xn[b,j]
//   T[j] = sum_b Xn[b,j]*r[b]
//   g[j] = 50/64 + 128 - 2*T[j]          (analytic grad; d==1 branch exact)
//   mask[j] = 1/64 - 0.01*g/(|g|+1e-8)
//   out = x * (1 + detal*mask[j])

#define IC   512
#define HW   4096
#define BB   8
#define NTOT (BB*HW)      // 32768
#define NCH  4
#define CPC  (IC/NCH)     // 128

__device__ float  g_part[NCH * NTOT];
__device__ float  g_m[NTOT];
__device__ float  g_xn[NTOT];
__device__ float  g_bsum[32];
__device__ float  g_bsum2[32];
__device__ float4 g_scale4[HW/4];

// ---------------- K1: channel-partial 1x1 conv --------------------------
// grid (NTOT/256, NCH), block 256. Each block: 256 consecutive (b,j), one
// c-chunk of 128 channels. Warp reads are 128B-line coalesced per channel.
__global__ void k1_conv_partial(const float* __restrict__ x,
                                const float* __restrict__ w) {
    __shared__ float sw[CPC];
    const int tid = threadIdx.x;
    const int c0  = blockIdx.y * CPC;
    if (tid < CPC) sw[tid] = w[c0 + tid];
    __syncthreads();

    const int n = blockIdx.x * 256 + tid;      // 0..32767
    const int b = n >> 12;                     // n / 4096
    const int j = n & (HW - 1);
    const float* xp = x + (size_t)b * IC * HW + (size_t)c0 * HW + j;

    float acc = 0.f;
    #pragma unroll 8
    for (int c = 0; c < CPC; ++c)
        acc += xp[(size_t)c * HW] * sw[c];

    g_part[blockIdx.y * NTOT + n] = acc;
}

// ---------------- K1b: merge partials + block stats ---------------------
// grid 32, block 256: each thread merges 4 outputs; block writes sum/sumsq.
__global__ void k1b_merge(const float* __restrict__ convb) {
    const int tid  = threadIdx.x;
    const int base = blockIdx.x * 1024;
    const float cb = convb[0];

    float s = 0.f, s2 = 0.f;
    #pragma unroll
    for (int i = 0; i < 4; ++i) {
        const int n = base + i * 256 + tid;
        float v = cb;
        #pragma unroll
        for (int ch = 0; ch < NCH; ++ch) v += g_part[ch * NTOT + n];
        g_m[n] = v;
        s += v; s2 += v * v;
    }

    __shared__ float rs[8], rs2[8];
    #pragma unroll
    for (int o = 16; o > 0; o >>= 1) {
        s  += __shfl_down_sync(0xffffffffu, s,  o);
        s2 += __shfl_down_sync(0xffffffffu, s2, o);
    }
    const int warp = tid >> 5, lane = tid & 31;
    if (lane == 0) { rs[warp] = s; rs2[warp] = s2; }
    __syncthreads();
    if (tid == 0) {
        float a = 0.f, a2 = 0.f;
        #pragma unroll
        for (int i = 0; i < 8; ++i) { a += rs[i]; a2 += rs2[i]; }
        g_bsum[blockIdx.x] = a; g_bsum2[blockIdx.x] = a2;
    }
}

// ---------------- K2: BN + PReLU + column-norm + mask -> scale ----------
// single block of 1024 threads; each thread owns 4 columns j (all 8 b's).
__global__ void __launch_bounds__(1024, 1)
k2_mask(const float* __restrict__ gamma, const float* __restrict__ beta,
        const float* __restrict__ pw,    const float* __restrict__ detal) {
    __shared__ float s_mu, s_rstd;
    __shared__ float s_r[8];
    __shared__ float s_warp[32][8];

    const int tid = threadIdx.x;

    // stats: reduce the 32 per-block sums
    if (tid < 32) {
        float s = g_bsum[tid], s2 = g_bsum2[tid];
        #pragma unroll
        for (int o = 16; o > 0; o >>= 1) {
            s  += __shfl_down_sync(0xffffffffu, s,  o);
            s2 += __shfl_down_sync(0xffffffffu, s2, o);
        }
        if (tid == 0) {
            const float mu  = s  * (1.0f / (float)NTOT);
            const float var = s2 * (1.0f / (float)NTOT) - mu * mu;
            s_mu   = mu;
            s_rstd = rsqrtf(var + 1e-5f);
        }
    }
    __syncthreads();

    const float mu = s_mu, rstd = s_rstd;
    const float ga = gamma[0], be = beta[0], p = pw[0];

    float rloc[8];
    #pragma unroll
    for (int b = 0; b < 8; ++b) rloc[b] = 0.f;

    #pragma unroll
    for (int k = 0; k < 4; ++k) {
        const int j = k * 1024 + tid;
        float X[8];
        float n2 = 0.f;
        #pragma unroll
        for (int b = 0; b < 8; ++b) {
            float v = g_m[b * HW + j];
            v = (v - mu) * rstd * ga + be;
            v = (v > 0.f) ? v : p * v;
            X[b] = v; n2 += v * v;
        }
        const float rs = rsqrtf(n2);
        #pragma unroll
        for (int b = 0; b < 8; ++b) {
            const float xn = X[b] * rs;
            rloc[b] += xn;
            g_xn[b * HW + j] = xn;     // reread by SAME thread below
        }
    }

    // reduce rloc[8] over 1024 threads
    const int warp = tid >> 5, lane = tid & 31;
    #pragma unroll
    for (int b = 0; b < 8; ++b)
        #pragma unroll
        for (int o = 16; o > 0; o >>= 1)
            rloc[b] += __shfl_down_sync(0xffffffffu, rloc[b], o);
    if (lane == 0) {
        #pragma unroll
        for (int b = 0; b < 8; ++b) s_warp[warp][b] = rloc[b];
    }
    __syncthreads();
    if (tid < 8) {
        float a = 0.f;
        #pragma unroll
        for (int wi = 0; wi < 32; ++wi) a += s_warp[wi][tid];
        s_r[tid] = a * (1.0f / 64.0f);      // r[b]
    }
    __syncthreads();

    const float r0 = s_r[0], r1 = s_r[1], r2 = s_r[2], r3 = s_r[3];
    const float r4 = s_r[4], r5 = s_r[5], r6 = s_r[6], r7 = s_r[7];
    const float dt = detal[0];
    float* g_scale = (float*)g_scale4;

    #pragma unroll
    for (int k = 0; k < 4; ++k) {
        const int j = k * 1024 + tid;
        const float T =
            g_xn[0 * HW + j] * r0 + g_xn[1 * HW + j] * r1 +
            g_xn[2 * HW + j] * r2 + g_xn[3 * HW + j] * r3 +
            g_xn[4 * HW + j] * r4 + g_xn[5 * HW + j] * r5 +
            g_xn[6 * HW + j] * r6 + g_xn[7 * HW + j] * r7;
        const float g    = 50.0f / 64.0f + 128.0f - 2.0f * T;
        const float u    = g / (fabsf(g) + 1e-8f);
        const float mask = (1.0f / 64.0f) - 0.01f * u;
        g_scale[j] = 1.0f + dt * mask;
    }
}

// ---------------- K3: out = x * scale[j], float4 ------------------------
__global__ void k3_apply(const float4* __restrict__ x4, float4* __restrict__ out4) {
    const int idx = blockIdx.x * 256 + threadIdx.x;     // float4 index
    const int j4  = idx & 1023;                         // plane = 1024 float4
    const float4 s = g_scale4[j4];
    float4 v = x4[idx];
    v.x *= s.x; v.y *= s.y; v.z *= s.z; v.w *= s.w;
    out4[idx] = v;
}

// ---------------- launch ------------------------------------------------
extern "C" void kernel_launch(void* const* d_in, const int* in_sizes, int n_in,
                              void* d_out, int out_size) {
    const float* x  = (const float*)d_in[0];
    const float* w  = (const float*)d_in[1];
    const float* cb = (const float*)d_in[2];
    const float* ga = (const float*)d_in[3];
    const float* be = (const float*)d_in[4];
    const float* pw = (const float*)d_in[5];
    const float* dt = (const float*)d_in[6];

    dim3 g1(NTOT / 256, NCH);
    k1_conv_partial<<<g1, 256>>>(x, w);
    k1b_merge<<<32, 256>>>(cb);
    k2_mask<<<1, 1024>>>(ga, be, pw, dt);
    k3_apply<<<(BB * IC * HW) / 4 / 256, 256>>>((const float4*)x, (float4*)d_out);
}

// round 3
// speedup vs baseline: 1.1492x; 1.1492x over previous
#include <cuda_runtime.h>

// Problem: B=8, IC=512, H=W=64
//   m[b,j]   = sum_c x[b,c,j]*w[c] + cb
//   BN(train, biased var) over all 32768 m, then PReLU -> X[b,j]
//   Xn = X / sqrt(sum_b X^2);  r[b] = (1/64) sum_j Xn;  T[j] = sum_b Xn*r[b]
//   g[j] = 50/64 + 128 - 2*T[j]  (analytic grad; d==1 branch exact)
//   mask[j] = 1/64 - 0.01*g/(|g|+1e-8);  out = x*(1 + detal*mask[j])

#define IC    512
#define HW    4096
#define HW4   1024        // float4 columns per plane
#define BB    8
#define NTOT  (BB*HW)     // 32768 scalars
#define N4    (BB*HW4)    // 8192 float4 (b,j4) positions
#define NCH   16
#define CPC   (IC/NCH)    // 32 channels per chunk

__device__ float4 g_part4[NCH * N4];   // 2 MiB scratch
__device__ float4 g_m4[N4];            // m, layout [b][j4]
__device__ float  g_xn[NTOT];
__device__ float  g_bsum[32];
__device__ float  g_bsum2[32];
__device__ float4 g_scale4[HW4];

// ---------------- K1: channel-partial 1x1 conv (float4 over j) ----------
// grid (32, NCH), block 256. Thread owns one (b,j4) and 32 channels.
__global__ void k1_conv_partial(const float4* __restrict__ x4,
                                const float* __restrict__ w) {
    __shared__ float sw[CPC];
    const int tid = threadIdx.x;
    const int ch  = blockIdx.y;
    const int c0  = ch * CPC;
    if (tid < CPC) sw[tid] = w[c0 + tid];
    __syncthreads();

    const int n4 = blockIdx.x * 256 + tid;     // 0..8191
    const int b  = n4 >> 10;
    const int j4 = n4 & (HW4 - 1);
    const float4* xp = x4 + (size_t)(b * IC + c0) * HW4 + j4;

    float4 acc = make_float4(0.f, 0.f, 0.f, 0.f);
    #pragma unroll 8
    for (int c = 0; c < CPC; ++c) {
        const float4 v  = xp[(size_t)c * HW4];
        const float  wc = sw[c];
        acc.x += v.x * wc; acc.y += v.y * wc;
        acc.z += v.z * wc; acc.w += v.w * wc;
    }
    g_part4[ch * N4 + n4] = acc;
}

// ---------------- K1b: merge partials + block stats ---------------------
// grid 32, block 256: each thread merges 16 partial float4s for one n4.
__global__ void k1b_merge(const float* __restrict__ convb) {
    const int tid = threadIdx.x;
    const int n4  = blockIdx.x * 256 + tid;    // 0..8191
    const float cb = convb[0];

    float4 v = make_float4(cb, cb, cb, cb);
    #pragma unroll
    for (int ch = 0; ch < NCH; ++ch) {
        const float4 p = g_part4[ch * N4 + n4];
        v.x += p.x; v.y += p.y; v.z += p.z; v.w += p.w;
    }
    g_m4[n4] = v;

    float s  = v.x + v.y + v.z + v.w;
    float s2 = v.x*v.x + v.y*v.y + v.z*v.z + v.w*v.w;

    __shared__ float rs[8], rs2[8];
    #pragma unroll
    for (int o = 16; o > 0; o >>= 1) {
        s  += __shfl_down_sync(0xffffffffu, s,  o);
        s2 += __shfl_down_sync(0xffffffffu, s2, o);
    }
    const int warp = tid >> 5, lane = tid & 31;
    if (lane == 0) { rs[warp] = s; rs2[warp] = s2; }
    __syncthreads();
    if (tid == 0) {
        float a = 0.f, a2 = 0.f;
        #pragma unroll
        for (int i = 0; i < 8; ++i) { a += rs[i]; a2 += rs2[i]; }
        g_bsum[blockIdx.x] = a; g_bsum2[blockIdx.x] = a2;
    }
}

// ---------------- K2: BN + PReLU + column-norm + mask -> scale ----------
// single block of 1024 threads; each thread owns 4 columns j (all 8 b's).
__global__ void __launch_bounds__(1024, 1)
k2_mask(const float* __restrict__ gamma, const float* __restrict__ beta,
        const float* __restrict__ pw,    const float* __restrict__ detal) {
    __shared__ float s_mu, s_rstd;
    __shared__ float s_r[8];
    __shared__ float s_warp[32][8];

    const int tid = threadIdx.x;
    const float* g_m = (const float*)g_m4;     // scalar view [b][j]

    if (tid < 32) {
        float s = g_bsum[tid], s2 = g_bsum2[tid];
        #pragma unroll
        for (int o = 16; o > 0; o >>= 1) {
            s  += __shfl_down_sync(0xffffffffu, s,  o);
            s2 += __shfl_down_sync(0xffffffffu, s2, o);
        }
        if (tid == 0) {
            const float mu  = s  * (1.0f / (float)NTOT);
            const float var = s2 * (1.0f / (float)NTOT) - mu * mu;
            s_mu   = mu;
            s_rstd = rsqrtf(var + 1e-5f);
        }
    }
    __syncthreads();

    const float mu = s_mu, rstd = s_rstd;
    const float ga = gamma[0], be = beta[0], p = pw[0];

    float rloc[8];
    #pragma unroll
    for (int b = 0; b < 8; ++b) rloc[b] = 0.f;

    #pragma unroll
    for (int k = 0; k < 4; ++k) {
        const int j = k * 1024 + tid;
        float X[8];
        float n2 = 0.f;
        #pragma unroll
        for (int b = 0; b < 8; ++b) {
            float v = g_m[b * HW + j];
            v = (v - mu) * rstd * ga + be;
            v = (v > 0.f) ? v : p * v;
            X[b] = v; n2 += v * v;
        }
        const float rs = rsqrtf(n2);
        #pragma unroll
        for (int b = 0; b < 8; ++b) {
            const float xn = X[b] * rs;
            rloc[b] += xn;
            g_xn[b * HW + j] = xn;     // reread by SAME thread below
        }
    }

    const int warp = tid >> 5, lane = tid & 31;
    #pragma unroll
    for (int b = 0; b < 8; ++b)
        #pragma unroll
        for (int o = 16; o > 0; o >>= 1)
            rloc[b] += __shfl_down_sync(0xffffffffu, rloc[b], o);
    if (lane == 0) {
        #pragma unroll
        for (int b = 0; b < 8; ++b) s_warp[warp][b] = rloc[b];
    }
    __syncthreads();
    if (tid < 8) {
        float a = 0.f;
        #pragma unroll
        for (int wi = 0; wi < 32; ++wi) a += s_warp[wi][tid];
        s_r[tid] = a * (1.0f / 64.0f);      // r[b]
    }
    __syncthreads();

    const float r0 = s_r[0], r1 = s_r[1], r2 = s_r[2], r3 = s_r[3];
    const float r4 = s_r[4], r5 = s_r[5], r6 = s_r[6], r7 = s_r[7];
    const float dt = detal[0];
    float* g_scale = (float*)g_scale4;

    #pragma unroll
    for (int k = 0; k < 4; ++k) {
        const int j = k * 1024 + tid;
        const float T =
            g_xn[0 * HW + j] * r0 + g_xn[1 * HW + j] * r1 +
            g_xn[2 * HW + j] * r2 + g_xn[3 * HW + j] * r3 +
            g_xn[4 * HW + j] * r4 + g_xn[5 * HW + j] * r5 +
            g_xn[6 * HW + j] * r6 + g_xn[7 * HW + j] * r7;
        const float g    = 50.0f / 64.0f + 128.0f - 2.0f * T;
        const float u    = g / (fabsf(g) + 1e-8f);
        const float mask = (1.0f / 64.0f) - 0.01f * u;
        g_scale[j] = 1.0f + dt * mask;
    }
}

// ---------------- K3: out = x * scale[j], 4 planes per thread -----------
// grid 4096, block 256. Thread t: j4 = t&1023, planes 4g..4g+3 (g=t>>10).
// One scale load feeds 4 independent float4 load/store pairs (MLP=4).
__global__ void k3_apply(const float4* __restrict__ x4, float4* __restrict__ out4) {
    const int t  = blockIdx.x * 256 + threadIdx.x;   // 0 .. 1048575
    const int j4 = t & (HW4 - 1);
    const int g  = t >> 10;                          // plane group 0..1023
    const float4 s = g_scale4[j4];
    const size_t base = (size_t)(g * 4) * HW4 + j4;

    float4 v0 = x4[base + 0 * HW4];
    float4 v1 = x4[base + 1 * HW4];
    float4 v2 = x4[base + 2 * HW4];
    float4 v3 = x4[base + 3 * HW4];
    v0.x *= s.x; v0.y *= s.y; v0.z *= s.z; v0.w *= s.w;
    v1.x *= s.x; v1.y *= s.y; v1.z *= s.z; v1.w *= s.w;
    v2.x *= s.x; v2.y *= s.y; v2.z *= s.z; v2.w *= s.w;
    v3.x *= s.x; v3.y *= s.y; v3.z *= s.z; v3.w *= s.w;
    out4[base + 0 * HW4] = v0;
    out4[base + 1 * HW4] = v1;
    out4[base + 2 * HW4] = v2;
    out4[base + 3 * HW4] = v3;
}

// ---------------- launch ------------------------------------------------
extern "C" void kernel_launch(void* const* d_in, const int* in_sizes, int n_in,
                              void* d_out, int out_size) {
    const float* x  = (const float*)d_in[0];
    const float* w  = (const float*)d_in[1];
    const float* cb = (const float*)d_in[2];
    const float* ga = (const float*)d_in[3];
    const float* be = (const float*)d_in[4];
    const float* pw = (const float*)d_in[5];
    const float* dt = (const float*)d_in[6];

    dim3 g1(N4 / 256, NCH);
    k1_conv_partial<<<g1, 256>>>((const float4*)x, w);
    k1b_merge<<<32, 256>>>(cb);
    k2_mask<<<1, 1024>>>(ga, be, pw, dt);
    k3_apply<<<4096, 256>>>((const float4*)x, (float4*)d_out);
}